// round 3
// baseline (speedup 1.0000x reference)
#include <cuda_runtime.h>
#include <cuda_bf16.h>

// GRU final-hidden: B=8192 independent scans, T<=2048 steps, I=1, H=3.
// One thread per batch element; entire recurrence in registers.
// blockDim=64 -> 128 CTAs over 148 SMs: each warp gets its own SMSP,
// so the per-step MUFU throughput (18 MUFU/step @ rt 8) is the binding pipe.

__device__ __forceinline__ float fsig(float u) {
    // 1/(1+exp(-u)); __expf = FMUL+MUFU.EX2, __fdividef = MUFU.RCP path. ~2ulp.
    float e = __expf(-u);
    return __fdividef(1.0f, 1.0f + e);
}

__device__ __forceinline__ float ftanh(float u) {
    // tanh(u) = 2/(1+exp(-2u)) - 1. Handles +/-inf saturation correctly.
    float e = __expf(-2.0f * u);
    return __fdividef(2.0f, 1.0f + e) - 1.0f;
}

__global__ __launch_bounds__(64, 1) void gru_seq_kernel(
    const float* __restrict__ x,      // [B, T, 1]
    const int*   __restrict__ lens,   // [B]
    const float* __restrict__ h0,     // [B, 3]
    const float* __restrict__ Wih,    // [9, 1]
    const float* __restrict__ Whh,    // [9, 3]
    const float* __restrict__ bih,    // [9]
    const float* __restrict__ bhh,    // [9]
    float* __restrict__ out,          // [1, B, 3]
    int B, int T)
{
    int b = blockIdx.x * blockDim.x + threadIdx.x;
    if (b >= B) return;
    int len = lens[b];
    if (len < 1) len = 1;
    if (len > T) len = T;

    // Weights in registers (uniform across threads; broadcast loads).
    float wx[9];
    float wh[9][3];
#pragma unroll
    for (int g = 0; g < 9; ++g) {
        wx[g] = Wih[g];
#pragma unroll
        for (int k = 0; k < 3; ++k) wh[g][k] = Whh[g * 3 + k];
    }
    // Fold b_ih+b_hh for r,z gates (the n gate needs them separate).
    float br[3], bz[3], bxn[3], bhn[3];
#pragma unroll
    for (int j = 0; j < 3; ++j) {
        br[j]  = bih[j]     + bhh[j];
        bz[j]  = bih[3 + j] + bhh[3 + j];
        bxn[j] = bih[6 + j];
        bhn[j] = bhh[6 + j];
    }

    float h[3];
#pragma unroll
    for (int j = 0; j < 3; ++j) h[j] = h0[b * 3 + j];

    // x row for this batch element: contiguous T floats, 16B-aligned (T=2048).
    const float4* xp = reinterpret_cast<const float4*>(x + (size_t)b * T);
    int nC = (len + 3) >> 2;

    float4 cur = xp[0];
    for (int c = 0; c < nC; ++c) {
        // Prefetch next chunk while computing 4 steps of this one.
        float4 nxt = (c + 1 < nC) ? xp[c + 1] : make_float4(0.f, 0.f, 0.f, 0.f);
        float xs[4] = {cur.x, cur.y, cur.z, cur.w};
#pragma unroll
        for (int k = 0; k < 4; ++k) {
            float xv = xs[k];
            float r[3], z[3], n[3];
#pragma unroll
            for (int j = 0; j < 3; ++j) {
                float ur = fmaf(wx[j], xv, br[j]);
                ur = fmaf(wh[j][2], h[2], fmaf(wh[j][1], h[1], fmaf(wh[j][0], h[0], ur)));
                float uz = fmaf(wx[3 + j], xv, bz[j]);
                uz = fmaf(wh[3 + j][2], h[2], fmaf(wh[3 + j][1], h[1], fmaf(wh[3 + j][0], h[0], uz)));
                float hn = fmaf(wh[6 + j][2], h[2], fmaf(wh[6 + j][1], h[1], fmaf(wh[6 + j][0], h[0], bhn[j])));
                float xn = fmaf(wx[6 + j], xv, bxn[j]);
                r[j] = fsig(ur);
                z[j] = fsig(uz);
                n[j] = ftanh(fmaf(r[j], hn, xn));
            }
            bool act = (4 * c + k) < len;
#pragma unroll
            for (int j = 0; j < 3; ++j) {
                // h' = (1-z)*n + z*h = n + z*(h-n), frozen once t >= len
                float hnew = fmaf(z[j], h[j] - n[j], n[j]);
                h[j] = act ? hnew : h[j];
            }
        }
        cur = nxt;
    }

    // Output = sigmoid(hT), layout [1, B, H]
#pragma unroll
    for (int j = 0; j < 3; ++j) out[b * 3 + j] = fsig(h[j]);
}

extern "C" void kernel_launch(void* const* d_in, const int* in_sizes, int n_in,
                              void* d_out, int out_size)
{
    const float* x   = (const float*)d_in[0];
    const int*   len = (const int*)  d_in[1];
    const float* h0  = (const float*)d_in[2];
    const float* Wih = (const float*)d_in[3];
    const float* Whh = (const float*)d_in[4];
    const float* bih = (const float*)d_in[5];
    const float* bhh = (const float*)d_in[6];
    float* out = (float*)d_out;

    int B = in_sizes[1];            // seq_lengths is [B]
    int T = in_sizes[0] / B;        // x is [B, T, 1]

    const int block = 64;           // 2 warps/CTA -> 128 CTAs: one warp per SMSP
    int grid = (B + block - 1) / block;
    gru_seq_kernel<<<grid, block>>>(x, len, h0, Wih, Whh, bih, bhh, out, B, T);
}

// round 4
// speedup vs baseline: 1.7879x; 1.7879x over previous
#include <cuda_runtime.h>
#include <cuda_bf16.h>

// GRU final-hidden: B=8192 independent scans, T<=2048, I=1, H=3.
// One thread per batch element; recurrence fully in registers.
// Latency-bound (occ 3.1%): the win is shortening the per-step activation
// chains. All activations via single-instruction MUFU tanh.approx.f32:
//   tanh(u)    -> tanh.approx
//   sigmoid(u) -> 0.5*tanh(0.5u)+0.5, with the 0.5 pre-folded into weights.

__device__ __forceinline__ float tanh_fast(float u) {
    float y;
    asm("tanh.approx.f32 %0, %1;" : "=f"(y) : "f"(u));
    return y;
}

__device__ __forceinline__ float fsig_accurate(float u) {
    // Used only for the single final output activation (cheap, off hot loop).
    float e = __expf(-u);
    return __fdividef(1.0f, 1.0f + e);
}

__global__ __launch_bounds__(64, 1) void gru_seq_kernel(
    const float* __restrict__ x,      // [B, T, 1]
    const int*   __restrict__ lens,   // [B]
    const float* __restrict__ h0,     // [B, 3]
    const float* __restrict__ Wih,    // [9, 1]
    const float* __restrict__ Whh,    // [9, 3]
    const float* __restrict__ bih,    // [9]
    const float* __restrict__ bhh,    // [9]
    float* __restrict__ out,          // [1, B, 3]
    int B, int T)
{
    int b = blockIdx.x * blockDim.x + threadIdx.x;
    if (b >= B) return;
    int len = lens[b];
    if (len < 1) len = 1;
    if (len > T) len = T;

    // Registers: r/z gate weights pre-scaled by 0.5 (sigmoid-via-tanh),
    // n gate weights unscaled.
    float wxr[3], wxz[3], wxn[3];
    float whr[3][3], whz[3][3], whn[3][3];
    float br[3], bz[3], bxn[3], bhn[3];
#pragma unroll
    for (int j = 0; j < 3; ++j) {
        wxr[j] = 0.5f * Wih[j];
        wxz[j] = 0.5f * Wih[3 + j];
        wxn[j] = Wih[6 + j];
#pragma unroll
        for (int k = 0; k < 3; ++k) {
            whr[j][k] = 0.5f * Whh[j * 3 + k];
            whz[j][k] = 0.5f * Whh[(3 + j) * 3 + k];
            whn[j][k] = Whh[(6 + j) * 3 + k];
        }
        br[j]  = 0.5f * (bih[j]     + bhh[j]);
        bz[j]  = 0.5f * (bih[3 + j] + bhh[3 + j]);
        bxn[j] = bih[6 + j];
        bhn[j] = bhh[6 + j];
    }

    float h[3];
#pragma unroll
    for (int j = 0; j < 3; ++j) h[j] = h0[b * 3 + j];

    // x row: contiguous T floats, 16B-aligned (T multiple of 4).
    const float4* xp = reinterpret_cast<const float4*>(x + (size_t)b * T);
    int nC = (len + 3) >> 2;

    float4 cur = xp[0];
    for (int c = 0; c < nC; ++c) {
        float4 nxt = (c + 1 < nC) ? xp[c + 1] : make_float4(0.f, 0.f, 0.f, 0.f);
        float xs[4] = {cur.x, cur.y, cur.z, cur.w};
#pragma unroll
        for (int k = 0; k < 4; ++k) {
            float xv = xs[k];
            float r[3], z[3], n[3];
#pragma unroll
            for (int j = 0; j < 3; ++j) {
                // ur, uz already scaled by 0.5 via weights.
                float ur = fmaf(wxr[j], xv, br[j]);
                ur = fmaf(whr[j][2], h[2], fmaf(whr[j][1], h[1], fmaf(whr[j][0], h[0], ur)));
                float uz = fmaf(wxz[j], xv, bz[j]);
                uz = fmaf(whz[j][2], h[2], fmaf(whz[j][1], h[1], fmaf(whz[j][0], h[0], uz)));
                float hn = fmaf(whn[j][2], h[2], fmaf(whn[j][1], h[1], fmaf(whn[j][0], h[0], bhn[j])));
                float xn = fmaf(wxn[j], xv, bxn[j]);
                r[j] = fmaf(tanh_fast(ur), 0.5f, 0.5f);   // sigmoid
                z[j] = fmaf(tanh_fast(uz), 0.5f, 0.5f);   // sigmoid
                n[j] = tanh_fast(fmaf(r[j], hn, xn));
            }
            bool act = (4 * c + k) < len;
#pragma unroll
            for (int j = 0; j < 3; ++j) {
                // h' = n + z*(h-n); frozen once t >= len.
                float hnew = fmaf(z[j], h[j] - n[j], n[j]);
                h[j] = act ? hnew : h[j];
            }
        }
        cur = nxt;
    }

    // Output = sigmoid(hT) with accurate sigmoid (3 calls total, off hot path).
#pragma unroll
    for (int j = 0; j < 3; ++j) out[b * 3 + j] = fsig_accurate(h[j]);
}

extern "C" void kernel_launch(void* const* d_in, const int* in_sizes, int n_in,
                              void* d_out, int out_size)
{
    const float* x   = (const float*)d_in[0];
    const int*   len = (const int*)  d_in[1];
    const float* h0  = (const float*)d_in[2];
    const float* Wih = (const float*)d_in[3];
    const float* Whh = (const float*)d_in[4];
    const float* bih = (const float*)d_in[5];
    const float* bhh = (const float*)d_in[6];
    float* out = (float*)d_out;

    int B = in_sizes[1];            // seq_lengths is [B]
    int T = in_sizes[0] / B;        // x is [B, T, 1]

    const int block = 64;
    int grid = (B + block - 1) / block;
    gru_seq_kernel<<<grid, block>>>(x, len, h0, Wih, Whh, bih, bhh, out, B, T);
}